// round 12
// baseline (speedup 1.0000x reference)
#include <cuda_runtime.h>
#include <cstdint>

// Problem: AveragePrecision_4690104287320
// output: (16,3,128,128,85) f32 -> 786,432 rows of 85 floats
// anchors: unused. targets: (16,50,5) f32 -> identity copy (fused in-kernel).
// Out: pred_out (786432 x 7 f32) then target copy (4000 f32).
//
// R12: R8/R11 champion + split-tile per-warp pipelining:
//   two 10,880 B TMA loads w/ independent mbarriers; each of the 2 warps
//   waits only on its own half, computes and stores independently
//   (__syncwarp epilogue; no block-wide barriers after launch).

#define CONF_THRESHOLD 0.25f

constexpr int ROWS    = 64;                 // rows per tile = threads per block
constexpr int WROWS   = 32;                 // rows per warp (half-tile)
constexpr int VROW    = 85;
constexpr int SMEM_F  = ROWS * VROW;        // 5440 floats
constexpr int HSMEM_F = WROWS * VROW;       // 2720 floats per half
constexpr int HTILE_B = HSMEM_F * 4;        // 10880 bytes per half (16B multiple)
constexpr int OUT_F   = ROWS * 7;           // 448 floats
constexpr int HOUT_F  = WROWS * 7;          // 224 floats per half
constexpr int HOUT_V4 = HOUT_F / 4;         // 56 float4 per half

__device__ __forceinline__ uint32_t smem_u32(const void* p) {
    uint32_t a;
    asm("{ .reg .u64 t; cvta.to.shared.u64 t, %1; cvt.u32.u64 %0, t; }" : "=r"(a) : "l"(p));
    return a;
}

__device__ __forceinline__ void mbar_wait0(uint32_t mb) {
    uint32_t done;
    asm volatile(
        "{\n\t.reg .pred p;\n\t"
        "mbarrier.try_wait.parity.acquire.cta.shared::cta.b64 p, [%1], %2;\n\t"
        "selp.b32 %0, 1, 0, p;\n\t}"
        : "=r"(done) : "r"(mb), "r"(0) : "memory");
    if (!done) {
        asm volatile(
            "{\n\t.reg .pred P1;\n\t"
            "WAIT_LOOP_%=:\n\t"
            "mbarrier.try_wait.parity.acquire.cta.shared::cta.b64 P1, [%0], %1, 0x989680;\n\t"
            "@P1 bra.uni WAIT_DONE_%=;\n\t"
            "bra.uni WAIT_LOOP_%=;\n\t"
            "WAIT_DONE_%=:\n\t}"
            :: "r"(mb), "r"(0) : "memory");
    }
}

__global__ void __launch_bounds__(ROWS)
yolo_fuse_kernel(const float* __restrict__ pred,
                 float4* __restrict__ out4,
                 const float4* __restrict__ targ4,
                 float4* __restrict__ targ_out4)
{
    __shared__ __align__(16) float smem[SMEM_F];
    __shared__ __align__(8) uint64_t mbar[2];

    const int tid  = threadIdx.x;
    const int wid  = tid >> 5;               // warp 0 / warp 1
    const int lane = tid & 31;
    const long long blk = blockIdx.x;
    const uint32_t mb0 = smem_u32(&mbar[0]);
    const uint32_t mb1 = smem_u32(&mbar[1]);

    // tid0: init both mbarriers, then issue BOTH half-tile DMAs back-to-back
    // (before any block-wide sync).
    if (tid == 0) {
        asm volatile("mbarrier.init.shared.b64 [%0], %1;" :: "r"(mb0), "r"(1) : "memory");
        asm volatile("mbarrier.init.shared.b64 [%0], %1;" :: "r"(mb1), "r"(1) : "memory");
        asm volatile("fence.mbarrier_init.release.cluster;" ::: "memory");
        const float* src = pred + blk * (long long)SMEM_F;
        asm volatile("mbarrier.arrive.expect_tx.shared.b64 _, [%0], %1;"
                     :: "r"(mb0), "r"((uint32_t)HTILE_B) : "memory");
        asm volatile("cp.async.bulk.shared::cta.global.mbarrier::complete_tx::bytes "
                     "[%0], [%1], %2, [%3];"
                     :: "r"(smem_u32(smem)), "l"(src),
                        "r"((uint32_t)HTILE_B), "r"(mb0) : "memory");
        asm volatile("mbarrier.arrive.expect_tx.shared.b64 _, [%0], %1;"
                     :: "r"(mb1), "r"((uint32_t)HTILE_B) : "memory");
        asm volatile("cp.async.bulk.shared::cta.global.mbarrier::complete_tx::bytes "
                     "[%0], [%1], %2, [%3];"
                     :: "r"(smem_u32(smem + HSMEM_F)), "l"(src + HSMEM_F),
                        "r"((uint32_t)HTILE_B), "r"(mb1) : "memory");
    }

    // ---- fused targets copy (1000 float4 over blocks 0..7, 2 chunks/thread) ----
    if (blk < 8) {
        int k0 = tid;           // 0..63
        int k1 = tid + 64;      // 64..127
        if (k0 < 125) targ_out4[(int)blk * 125 + k0] = targ4[(int)blk * 125 + k0];
        if (k1 < 125) targ_out4[(int)blk * 125 + k1] = targ4[(int)blk * 125 + k1];
    }

    // all threads must observe the initialized mbarriers before waiting
    __syncthreads();

    // ---- each warp waits only on its own half ----
    float* hbuf = smem + wid * HSMEM_F;
    mbar_wait0(wid ? mb1 : mb0);

    // ---- thread-per-row scan (stride-85 floats: bank-conflict-free) ----
    const float* row = hbuf + lane * VROW;
    const float b0 = row[0], b1 = row[1], b2 = row[2], b3 = row[3];
    const float obj = row[4];

    float m0 = row[5], m1 = row[6], m2 = row[7], m3 = row[8];
    int   i0 = 0,      i1 = 1,      i2 = 2,      i3 = 3;
    #pragma unroll
    for (int k = 1; k < 20; k++) {
        const float v0 = row[5 + 4 * k];
        const float v1 = row[6 + 4 * k];
        const float v2 = row[7 + 4 * k];
        const float v3 = row[8 + 4 * k];
        if (v0 > m0) { m0 = v0; i0 = 4 * k;     }
        if (v1 > m1) { m1 = v1; i1 = 4 * k + 1; }
        if (v2 > m2) { m2 = v2; i2 = 4 * k + 2; }
        if (v3 > m3) { m3 = v3; i3 = 4 * k + 3; }
    }
    float best = m0; int bidx = i0;
    if (m1 > best || (m1 == best && i1 < bidx)) { best = m1; bidx = i1; }
    if (m2 > best || (m2 == best && i2 < bidx)) { best = m2; bidx = i2; }
    if (m3 > best || (m3 == best && i3 < bidx)) { best = m3; bidx = i3; }

    const float conf = best * obj;
    const bool  keep = conf > CONF_THRESHOLD;

    float r[7];
    r[0] = keep ? b0 : 0.0f;
    r[1] = keep ? b1 : 0.0f;
    r[2] = keep ? b2 : 0.0f;
    r[3] = keep ? b3 : 0.0f;
    r[4] = keep ? obj : 0.0f;
    r[5] = keep ? (float)bidx : 0.0f;
    r[6] = keep ? conf : 0.0f;

    // ---- per-warp epilogue: stage (stride-7, conflict-free) and store ----
    __syncwarp();                    // all lanes of this warp done reading hbuf
    #pragma unroll
    for (int j = 0; j < 7; j++) hbuf[lane * 7 + j] = r[j];
    __syncwarp();

    const float4* s4 = reinterpret_cast<const float4*>(hbuf);
    float4* dst = out4 + (blk * 2 + wid) * HOUT_V4;
    __stcs(dst + lane, s4[lane]);                   // idx 0..31
    if (lane < HOUT_V4 - 32)                        // idx 32..55
        __stcs(dst + lane + 32, s4[lane + 32]);
}

extern "C" void kernel_launch(void* const* d_in, const int* in_sizes, int n_in,
                              void* d_out, int out_size)
{
    const float* output  = (const float*)d_in[0];   // (16,3,128,128,85)
    const float* targets = (const float*)d_in[2];   // (16,50,5)

    float* out = (float*)d_out;

    const int nrows = in_sizes[0] / VROW;           // 786432 (multiple of 64)
    float* targ_out = out + (long long)nrows * 7;

    const int grid = nrows / ROWS;                  // 12288 blocks
    yolo_fuse_kernel<<<grid, ROWS>>>(output, (float4*)out,
                                     (const float4*)targets, (float4*)targ_out);
}